// round 2
// baseline (speedup 1.0000x reference)
#include <cuda_runtime.h>
#include <cstdint>

#define TPB 128
#define XPAD 62   // per-problem smem stride in floats (even -> 8B-aligned float2; 62%32=30 -> only 2-way bank conflicts)

typedef unsigned long long ull;

// ---- packed fp32x2 helpers (FFMA2 via PTX fma.rn.f32x2) ----
__device__ __forceinline__ ull pk(float lo, float hi) {
    ull r; asm("mov.b64 %0, {%1, %2};" : "=l"(r) : "f"(lo), "f"(hi)); return r;
}
__device__ __forceinline__ float lo2(ull v) { return __uint_as_float((unsigned)v); }
__device__ __forceinline__ float hi2(ull v) { return __uint_as_float((unsigned)(v >> 32)); }
__device__ __forceinline__ ull fma2(ull a, ull b, ull c) {
    ull d; asm("fma.rn.f32x2 %0, %1, %2, %3;" : "=l"(d) : "l"(a), "l"(b), "l"(c)); return d;
}
__device__ __forceinline__ ull add2(ull a, ull b) {
    ull d; asm("add.rn.f32x2 %0, %1, %2;" : "=l"(d) : "l"(a), "l"(b)); return d;
}
__device__ __forceinline__ float ex2(float x) {
    float r; asm("ex2.approx.f32 %0, %1;" : "=f"(r) : "f"(x)); return r;
}

// Constant layout (duplicated float2 pairs; score-terms pre-scaled by log2(e)):
// [0..35]  Mp   = (Wq^T Wk) * L2E      (M[a*6+d])
// [36..41] up   = (Wq^T bk) * L2E
// [42..47] rp   = (Wk^T bq) * L2E
// [48..53] wvp  = colsum(Wv)           (unscaled)
// [54]     c0p  = (bq.bk) * L2E
// [55]     cvp  = sum(bv)              (unscaled)
__device__   float2 g_cst[56];
__constant__ float2 c_cst[56];

__global__ void precompute_kernel(
    const float* __restrict__ Wk, const float* __restrict__ bk,
    const float* __restrict__ Wq, const float* __restrict__ bq,
    const float* __restrict__ Wv, const float* __restrict__ bv)
{
    const int t = threadIdx.x;
    const float L2E = 1.4426950408889634f;
    float s = 0.f;
    if (t < 36) {
        int a = t / 6, b = t % 6;
        #pragma unroll
        for (int e = 0; e < 6; e++) s += Wq[e*6 + a] * Wk[e*6 + b];
        s *= L2E;
    } else if (t < 42) {
        int a = t - 36;
        #pragma unroll
        for (int e = 0; e < 6; e++) s += Wq[e*6 + a] * bk[e];
        s *= L2E;
    } else if (t < 48) {
        int b = t - 42;
        #pragma unroll
        for (int e = 0; e < 6; e++) s += bq[e] * Wk[e*6 + b];
        s *= L2E;
    } else if (t < 54) {
        int d = t - 48;
        #pragma unroll
        for (int e = 0; e < 6; e++) s += Wv[e*6 + d];
    } else if (t == 54) {
        #pragma unroll
        for (int e = 0; e < 6; e++) s += bq[e] * bk[e];
        s *= L2E;
    } else {
        #pragma unroll
        for (int e = 0; e < 6; e++) s += bv[e];
    }
    if (t < 56) g_cst[t] = make_float2(s, s);
}

// One thread = one batch problem.
// S_ij*L2E = x_i^T M x_j + x_i.u + r.x_j + c   (all pre-scaled), softmax via ex2.
// out_i = sum_j 2^{S_ij} vsum_j / sum_j 2^{S_ij},  vsum_j = wv.x_j + cv
__global__ __launch_bounds__(TPB, 4) void attn_kernel(
    const float* __restrict__ x, float* __restrict__ out)
{
    __shared__ float xs[TPB * XPAD];
    const int t = threadIdx.x;
    const ull* C = reinterpret_cast<const ull*>(c_cst);

    // ---- coalesced staging: 128 problems * 60 floats = 1920 float4 per block ----
    const float4* xg = (const float4*)(x + (size_t)blockIdx.x * (TPB * 60));
    #pragma unroll
    for (int i = 0; i < 15; i++) {
        float4 v = xg[i * TPB + t];
        int g = (i * TPB + t) * 4;       // 60 % 4 == 0 -> float4 never crosses a problem boundary
        int b = g / 60, e = g % 60;
        float2* dst = (float2*)&xs[b * XPAD + e];   // (b*62+e) even -> 8B aligned
        dst[0] = make_float2(v.x, v.y);
        dst[1] = make_float2(v.z, v.w);
    }
    __syncthreads();

    const float*  xp  = &xs[t * XPAD];
    const float2* xv2 = (const float2*)xp;

    // ---- phase 1 (packed over key pairs): G_j[a] = (M x_j + u)[a], h_j, vsum_j ----
    ull G2[6][5], hp[5], vp[5];
    #pragma unroll
    for (int jp = 0; jp < 5; jp++) {
        float2 p0 = xv2[jp*6 + 0], p1 = xv2[jp*6 + 1], p2 = xv2[jp*6 + 2];
        float2 p3 = xv2[jp*6 + 3], p4 = xv2[jp*6 + 4], p5 = xv2[jp*6 + 5];
        ull xx[6];
        xx[0] = pk(p0.x, p3.x); xx[1] = pk(p0.y, p3.y);
        xx[2] = pk(p1.x, p4.x); xx[3] = pk(p1.y, p4.y);
        xx[4] = pk(p2.x, p5.x); xx[5] = pk(p2.y, p5.y);

        ull g[6];
        #pragma unroll
        for (int a = 0; a < 6; a++) g[a] = C[36 + a];
        ull h = C[54], v = C[55];
        #pragma unroll
        for (int d = 0; d < 6; d++) {
            #pragma unroll
            for (int a = 0; a < 6; a++) g[a] = fma2(C[a*6 + d], xx[d], g[a]);
            h = fma2(C[42 + d], xx[d], h);
            v = fma2(C[48 + d], xx[d], v);
        }
        #pragma unroll
        for (int a = 0; a < 6; a++) G2[a][jp] = g[a];
        hp[jp] = h;
        vp[jp] = v;
    }

    // ---- phase 2: per query, 2 scores at a time; fused softmax + weighted sum ----
    float res[10];
    #pragma unroll
    for (int i = 0; i < 10; i++) {
        ull X[6];
        #pragma unroll
        for (int a = 0; a < 6; a++) { float xv = xp[i*6 + a]; X[a] = pk(xv, xv); }
        ull num2 = 0, den2 = 0;
        #pragma unroll
        for (int jp = 0; jp < 5; jp++) {
            ull s = hp[jp];
            #pragma unroll
            for (int a = 0; a < 6; a++) s = fma2(X[a], G2[a][jp], s);
            float ea = ex2(lo2(s));
            float eb = ex2(hi2(s));
            ull e2 = pk(ea, eb);
            num2 = fma2(e2, vp[jp], num2);
            den2 = add2(den2, e2);
        }
        res[i] = __fdividef(lo2(num2) + hi2(num2), lo2(den2) + hi2(den2));
    }

    // ---- output: 5 x float2 per thread (40B-aligned base -> 8B ok) ----
    float2* op = (float2*)(out + (size_t)(blockIdx.x * TPB + t) * 10);
    #pragma unroll
    for (int p = 0; p < 5; p++) op[p] = make_float2(res[2*p], res[2*p + 1]);
}

extern "C" void kernel_launch(void* const* d_in, const int* in_sizes, int n_in,
                              void* d_out, int out_size) {
    const float* x  = (const float*)d_in[0];
    const float* Wk = (const float*)d_in[1];
    const float* bk = (const float*)d_in[2];
    const float* Wq = (const float*)d_in[3];
    const float* bq = (const float*)d_in[4];
    const float* Wv = (const float*)d_in[5];
    const float* bv = (const float*)d_in[6];

    precompute_kernel<<<1, 64>>>(Wk, bk, Wq, bq, Wv, bv);

    void* src = nullptr;
    cudaGetSymbolAddress(&src, g_cst);
    cudaMemcpyToSymbolAsync(c_cst, src, 56 * sizeof(float2), 0,
                            cudaMemcpyDeviceToDevice, 0);

    int B = in_sizes[0] / 60;            // 524288
    int blocks = B / TPB;                // 4096
    attn_kernel<<<blocks, TPB>>>(x, (float*)d_out);
}

// round 3
// speedup vs baseline: 1.0768x; 1.0768x over previous
#include <cuda_runtime.h>

#define TPB 128
#define XPAD 63   // odd stride: t*63 mod 32 is a bijection -> conflict-free per-thread LDS.32

typedef unsigned long long ull;

// ---- packed fp32x2 helpers (FFMA2 via PTX fma.rn.f32x2) ----
__device__ __forceinline__ ull pk(float lo, float hi) {
    ull r; asm("mov.b64 %0, {%1, %2};" : "=l"(r) : "f"(lo), "f"(hi)); return r;
}
__device__ __forceinline__ float lo2(ull v) { return __uint_as_float((unsigned)v); }
__device__ __forceinline__ float hi2(ull v) { return __uint_as_float((unsigned)(v >> 32)); }
__device__ __forceinline__ ull fma2(ull a, ull b, ull c) {
    ull d; asm("fma.rn.f32x2 %0, %1, %2, %3;" : "=l"(d) : "l"(a), "l"(b), "l"(c)); return d;
}
__device__ __forceinline__ ull add2(ull a, ull b) {
    ull d; asm("add.rn.f32x2 %0, %1, %2;" : "=l"(d) : "l"(a), "l"(b)); return d;
}
__device__ __forceinline__ float ex2(float x) {
    float r; asm("ex2.approx.f32 %0, %1;" : "=f"(r) : "f"(x)); return r;
}

// One thread = one batch problem.
// S_ij * log2(e) = x_i^T M x_j + x_i.u + r.x_j + c   (M,u,r,c pre-scaled by log2e)
// out_i = sum_j 2^{S'_ij} vsum_j / sum_j 2^{S'_ij},  vsum_j = wv.x_j + cv
//
// smem constant layout (duplicated float2 pairs, directly usable as fma2 operands):
// [0..35] M (a*6+d), [36..41] u, [42..47] r, [48..53] wv, [54] c, [55] cv
__global__ __launch_bounds__(TPB, 4) void attn_kernel(
    const float* __restrict__ x,
    const float* __restrict__ Wk, const float* __restrict__ bk,
    const float* __restrict__ Wq, const float* __restrict__ bq,
    const float* __restrict__ Wv, const float* __restrict__ bv,
    float* __restrict__ out)
{
    __shared__ float2 cst[56];
    __shared__ float  xs[TPB * XPAD];
    const int t = threadIdx.x;

    // ---- per-block precompute of dup-packed constants (L2-cached W reads) ----
    if (t < 56) {
        const float L2E = 1.4426950408889634f;
        float s = 0.f;
        if (t < 36) {                    // M[a][b] = sum_e Wq[e][a] Wk[e][b]  (*L2E)
            int a = t / 6, b = t % 6;
            #pragma unroll
            for (int e = 0; e < 6; e++) s += Wq[e*6 + a] * Wk[e*6 + b];
            s *= L2E;
        } else if (t < 42) {             // u[a] = sum_e Wq[e][a] bk[e]  (*L2E)
            int a = t - 36;
            #pragma unroll
            for (int e = 0; e < 6; e++) s += Wq[e*6 + a] * bk[e];
            s *= L2E;
        } else if (t < 48) {             // r[b] = sum_e bq[e] Wk[e][b]  (*L2E)
            int b = t - 42;
            #pragma unroll
            for (int e = 0; e < 6; e++) s += bq[e] * Wk[e*6 + b];
            s *= L2E;
        } else if (t < 54) {             // wv[d] = colsum(Wv)
            int d = t - 48;
            #pragma unroll
            for (int e = 0; e < 6; e++) s += Wv[e*6 + d];
        } else if (t == 54) {            // c = bq.bk (*L2E)
            #pragma unroll
            for (int e = 0; e < 6; e++) s += bq[e] * bk[e];
            s *= L2E;
        } else {                         // cv = sum(bv)
            #pragma unroll
            for (int e = 0; e < 6; e++) s += bv[e];
        }
        cst[t] = make_float2(s, s);
    }

    // ---- coalesced staging: 128 problems * 60 floats, scalar scatter (XPAD odd) ----
    const float4* xg = (const float4*)(x + (size_t)blockIdx.x * (TPB * 60));
    #pragma unroll
    for (int i = 0; i < 15; i++) {
        float4 v = xg[i * TPB + t];
        int g = (i * TPB + t) * 4;       // 60 % 4 == 0 -> float4 never crosses a problem
        int b = g / 60, e = g % 60;
        float* dst = &xs[b * XPAD + e];
        dst[0] = v.x; dst[1] = v.y; dst[2] = v.z; dst[3] = v.w;
    }
    __syncthreads();

    const float* xp = &xs[t * XPAD];
    const ull*   C  = reinterpret_cast<const ull*>(cst);

    // ---- phase 1, d-outer: each constant and each x element loaded exactly once ----
    // G[a][jp] = ((M x_j + u)[a], (M x_{j+1} + u)[a]);  hp = (h_j, h_j+1);  vp = (vsum_j, vsum_j+1)
    ull G[6][5], hp[5], vp[5];
    {   // d = 0: fold init (c-operand = u/c/cv) into the first fma2
        ull xx[5];
        #pragma unroll
        for (int jp = 0; jp < 5; jp++) xx[jp] = pk(xp[jp*12 + 0], xp[jp*12 + 6 + 0]);
        #pragma unroll
        for (int a = 0; a < 6; a++) {
            ull m = C[a*6 + 0], u = C[36 + a];
            #pragma unroll
            for (int jp = 0; jp < 5; jp++) G[a][jp] = fma2(m, xx[jp], u);
        }
        ull r = C[42], w = C[48], c0 = C[54], cv = C[55];
        #pragma unroll
        for (int jp = 0; jp < 5; jp++) { hp[jp] = fma2(r, xx[jp], c0); vp[jp] = fma2(w, xx[jp], cv); }
    }
    #pragma unroll
    for (int d = 1; d < 6; d++) {
        ull xx[5];
        #pragma unroll
        for (int jp = 0; jp < 5; jp++) xx[jp] = pk(xp[jp*12 + d], xp[jp*12 + 6 + d]);
        #pragma unroll
        for (int a = 0; a < 6; a++) {
            ull m = C[a*6 + d];
            #pragma unroll
            for (int jp = 0; jp < 5; jp++) G[a][jp] = fma2(m, xx[jp], G[a][jp]);
        }
        ull r = C[42 + d], w = C[48 + d];
        #pragma unroll
        for (int jp = 0; jp < 5; jp++) { hp[jp] = fma2(r, xx[jp], hp[jp]); vp[jp] = fma2(w, xx[jp], vp[jp]); }
    }

    // ---- phase 2: per query, 2 scores at a time; fused softmax + weighted sum ----
    float res[10];
    #pragma unroll
    for (int i = 0; i < 10; i++) {
        ull X[6];
        #pragma unroll
        for (int a = 0; a < 6; a++) { float xv = xp[i*6 + a]; X[a] = pk(xv, xv); }
        ull num = 0, den = 0;
        #pragma unroll
        for (int jp = 0; jp < 5; jp++) {
            ull s = hp[jp];
            #pragma unroll
            for (int a = 0; a < 6; a++) s = fma2(X[a], G[a][jp], s);
            float ea = ex2(lo2(s));
            float eb = ex2(hi2(s));
            ull e2 = pk(ea, eb);
            num = fma2(e2, vp[jp], num);
            den = add2(den, e2);
        }
        res[i] = __fdividef(lo2(num) + hi2(num), lo2(den) + hi2(den));
    }

    // ---- output: 5 x float2 per thread ----
    float2* op = (float2*)(out + (size_t)(blockIdx.x * TPB + t) * 10);
    #pragma unroll
    for (int p = 0; p < 5; p++) op[p] = make_float2(res[2*p], res[2*p + 1]);
}

extern "C" void kernel_launch(void* const* d_in, const int* in_sizes, int n_in,
                              void* d_out, int out_size) {
    const float* x  = (const float*)d_in[0];
    const float* Wk = (const float*)d_in[1];
    const float* bk = (const float*)d_in[2];
    const float* Wq = (const float*)d_in[3];
    const float* bq = (const float*)d_in[4];
    const float* Wv = (const float*)d_in[5];
    const float* bv = (const float*)d_in[6];
    int B = in_sizes[0] / 60;            // 524288
    int blocks = B / TPB;                // 4096
    attn_kernel<<<blocks, TPB>>>(x, Wk, bk, Wq, bq, Wv, bv, (float*)d_out);
}